// round 6
// baseline (speedup 1.0000x reference)
#include <cuda_runtime.h>
#include <cuda_bf16.h>

#define Bb 4
#define Hh 200
#define Ww 200
#define Tt 5
#define C4 16                 // float4 per 64-channel dim
#define PIX_F4 (Tt * C4)      // 80 float4 per (b,h,w) pixel

// Block = 4(w) x 4(h) pixel tile x 16 c4 = 256 threads.
// 50 x 50 tiles per batch. Supertile = 5x5 tiles (20x20 px) = 25 blocks.
// 100 supertiles per batch, 2500 blocks per batch, 10000 total.
#define TILES_X 50
#define BLOCKS_PER_BATCH (TILES_X * TILES_X)   // 2500
#define BLOCKS_PER_ST 25
#define ST_X 10                                // 10 supertiles across
#define TOTAL_BLOCKS (Bb * BLOCKS_PER_BATCH)   // 10000

__global__ __launch_bounds__(256, 4) void align_bev_sq(
    const float4* __restrict__ in,
    const float*  __restrict__ ego,
    float4* __restrict__ out)
{
    // ---- block -> 4x4 pixel tile (supertile-ordered) ----
    int bid   = blockIdx.x;
    int b     = bid / BLOCKS_PER_BATCH;
    int r     = bid - b * BLOCKS_PER_BATCH;
    int st    = r / BLOCKS_PER_ST;          // 0..99
    int inner = r - st * BLOCKS_PER_ST;     // 0..24
    int stx   = st % ST_X;
    int sty   = st / ST_X;
    int tx    = inner % 5;
    int ty    = inner / 5;
    int tile_x = stx * 5 + tx;              // 0..49
    int tile_y = sty * 5 + ty;              // 0..49

    int c4 = threadIdx.x & 15;
    int px = threadIdx.x >> 4;              // 0..15 pixel within 4x4 tile
    int w  = tile_x * 4 + (px & 3);
    int h  = tile_y * 4 + (px >> 2);

    int pix = (b * Hh + h) * Ww + w;

    // ---- per-pixel transform ----
    float dxn  = ego[3 * b + 0] * 0.01f;    // / (MAP_RANGE/2 = 100)
    float dyn  = ego[3 * b + 1] * 0.01f;
    float dyaw = ego[3 * b + 2];

    float s, c;
    sincosf(dyaw, &s, &c);
    float tfx = -(c * dxn + s * dyn);
    float tfy =  s * dxn - c * dyn;

    const float invW = 1.0f / (float)Ww;
    const float invH = 1.0f / (float)Hh;
    float xsv = (2.0f * (float)w + 1.0f) * invW - 1.0f;
    float ysv = (2.0f * (float)h + 1.0f) * invH - 1.0f;

    float gx =  c * xsv + s * ysv + tfx;
    float gy = -s * xsv + c * ysv + tfy;

    float ixv = ((gx + 1.0f) * (float)Ww - 1.0f) * 0.5f;
    float iyv = ((gy + 1.0f) * (float)Hh - 1.0f) * 0.5f;

    float ix0f = floorf(ixv);
    float iy0f = floorf(iyv);
    float wx1 = ixv - ix0f, wx0 = 1.0f - wx1;
    float wy1 = iyv - iy0f, wy0 = 1.0f - wy1;
    float ix1f = ix0f + 1.0f;
    float iy1f = iy0f + 1.0f;

    float mx0 = (ix0f >= 0.0f && ix0f <= (float)(Ww - 1)) ? 1.0f : 0.0f;
    float mx1 = (ix1f >= 0.0f && ix1f <= (float)(Ww - 1)) ? 1.0f : 0.0f;
    float my0 = (iy0f >= 0.0f && iy0f <= (float)(Hh - 1)) ? 1.0f : 0.0f;
    float my1 = (iy1f >= 0.0f && iy1f <= (float)(Hh - 1)) ? 1.0f : 0.0f;

    int x0 = (int)fminf(fmaxf(ix0f, 0.0f), (float)(Ww - 1));
    int x1 = (int)fminf(fmaxf(ix1f, 0.0f), (float)(Ww - 1));
    int y0 = (int)fminf(fmaxf(iy0f, 0.0f), (float)(Hh - 1));
    int y1 = (int)fminf(fmaxf(iy1f, 0.0f), (float)(Hh - 1));

    float w00 = wy0 * wx0 * (my0 * mx0);
    float w01 = wy0 * wx1 * (my0 * mx1);
    float w10 = wy1 * wx0 * (my1 * mx0);
    float w11 = wy1 * wx1 * (my1 * mx1);

    int baseB = b * (Hh * Ww);
    int o00 = (baseB + y0 * Ww + x0) * PIX_F4 + c4;
    int o01 = (baseB + y0 * Ww + x1) * PIX_F4 + c4;
    int o10 = (baseB + y1 * Ww + x0) * PIX_F4 + c4;
    int o11 = (baseB + y1 * Ww + x1) * PIX_F4 + c4;

    int outbase = pix * PIX_F4 + c4;
    int tc4 = (Tt - 1) * C4;

    // ---- front-load all 17 loads (max MLP), then blend ----
    float4 a00 = __ldg(&in[o00 +  0]);
    float4 a01 = __ldg(&in[o01 +  0]);
    float4 a10 = __ldg(&in[o10 +  0]);
    float4 a11 = __ldg(&in[o11 +  0]);
    float4 b00 = __ldg(&in[o00 + 16]);
    float4 b01 = __ldg(&in[o01 + 16]);
    float4 b10 = __ldg(&in[o10 + 16]);
    float4 b11 = __ldg(&in[o11 + 16]);
    float4 e00 = __ldg(&in[o00 + 32]);
    float4 e01 = __ldg(&in[o01 + 32]);
    float4 e10 = __ldg(&in[o10 + 32]);
    float4 e11 = __ldg(&in[o11 + 32]);
    float4 f00 = __ldg(&in[o00 + 48]);
    float4 f01 = __ldg(&in[o01 + 48]);
    float4 f10 = __ldg(&in[o10 + 48]);
    float4 f11 = __ldg(&in[o11 + 48]);
    float4 cur = __ldcs(&in[outbase + tc4]);

    float4 r0, r1, r2, r3;
    r0.x = w00*a00.x + w01*a01.x + w10*a10.x + w11*a11.x;
    r0.y = w00*a00.y + w01*a01.y + w10*a10.y + w11*a11.y;
    r0.z = w00*a00.z + w01*a01.z + w10*a10.z + w11*a11.z;
    r0.w = w00*a00.w + w01*a01.w + w10*a10.w + w11*a11.w;
    r1.x = w00*b00.x + w01*b01.x + w10*b10.x + w11*b11.x;
    r1.y = w00*b00.y + w01*b01.y + w10*b10.y + w11*b11.y;
    r1.z = w00*b00.z + w01*b01.z + w10*b10.z + w11*b11.z;
    r1.w = w00*b00.w + w01*b01.w + w10*b10.w + w11*b11.w;
    __stcs(&out[outbase +  0], r0);
    __stcs(&out[outbase + 16], r1);

    r2.x = w00*e00.x + w01*e01.x + w10*e10.x + w11*e11.x;
    r2.y = w00*e00.y + w01*e01.y + w10*e10.y + w11*e11.y;
    r2.z = w00*e00.z + w01*e01.z + w10*e10.z + w11*e11.z;
    r2.w = w00*e00.w + w01*e01.w + w10*e10.w + w11*e11.w;
    r3.x = w00*f00.x + w01*f01.x + w10*f10.x + w11*f11.x;
    r3.y = w00*f00.y + w01*f01.y + w10*f10.y + w11*f11.y;
    r3.z = w00*f00.z + w01*f01.z + w10*f10.z + w11*f11.z;
    r3.w = w00*f00.w + w01*f01.w + w10*f10.w + w11*f11.w;
    __stcs(&out[outbase + 32], r2);
    __stcs(&out[outbase + 48], r3);

    __stcs(&out[outbase + tc4], cur);
}

extern "C" void kernel_launch(void* const* d_in, const int* in_sizes, int n_in,
                              void* d_out, int out_size)
{
    const float4* in  = (const float4*)d_in[0];   // raw_bev_cache (4,200,200,5,64) f32
    const float*  ego = (const float*)d_in[1];    // delta_ego_motion (4,3) f32
    float4* out = (float4*)d_out;

    align_bev_sq<<<TOTAL_BLOCKS, 256>>>(in, ego, out);
}

// round 7
// speedup vs baseline: 1.0048x; 1.0048x over previous
#include <cuda_runtime.h>
#include <cuda_bf16.h>

#define Bb 4
#define Hh 200
#define Ww 200
#define Tt 5
#define C4 16                 // float4 per 64-channel dim
#define PIX_F4 (Tt * C4)      // 80 float4 per (b,h,w) pixel
#define NPIX (Bb * Hh * Ww)   // 160,000
#define PIX_PER_BLOCK 8
#define NBLOCKS (NPIX / PIX_PER_BLOCK)   // 20,000

struct PixS {
    float w00, w01, w10, w11;
    int   o00, o01, o10, o11;   // corner base offsets (float4 units), without c4
    int   ob;                   // output base (float4 units), without c4
};

__global__ __launch_bounds__(256, 5) void align_bev_v7(
    const float4* __restrict__ in,
    const float*  __restrict__ ego,
    float4* __restrict__ out)
{
    __shared__ PixS sm[PIX_PER_BLOCK];

    int tid = threadIdx.x;

    // ---- threads 0..7: per-pixel transform into smem ----
    if (tid < PIX_PER_BLOCK) {
        int pix = blockIdx.x * PIX_PER_BLOCK + tid;
        int w  = pix % Ww;
        int hb = pix / Ww;
        int h  = hb % Hh;
        int b  = hb / Hh;

        float dxn  = ego[3 * b + 0] * 0.01f;   // / (MAP_RANGE/2 = 100)
        float dyn  = ego[3 * b + 1] * 0.01f;
        float dyaw = ego[3 * b + 2];

        float s, c;
        sincosf(dyaw, &s, &c);
        float tfx = -(c * dxn + s * dyn);
        float tfy =  s * dxn - c * dyn;

        float xsv = (2.0f * (float)w + 1.0f) * (1.0f / (float)Ww) - 1.0f;
        float ysv = (2.0f * (float)h + 1.0f) * (1.0f / (float)Hh) - 1.0f;

        float gx =  c * xsv + s * ysv + tfx;
        float gy = -s * xsv + c * ysv + tfy;

        float ixv = ((gx + 1.0f) * (float)Ww - 1.0f) * 0.5f;
        float iyv = ((gy + 1.0f) * (float)Hh - 1.0f) * 0.5f;

        float ix0f = floorf(ixv);
        float iy0f = floorf(iyv);
        float wx1 = ixv - ix0f, wx0 = 1.0f - wx1;
        float wy1 = iyv - iy0f, wy0 = 1.0f - wy1;
        float ix1f = ix0f + 1.0f;
        float iy1f = iy0f + 1.0f;

        float mx0 = (ix0f >= 0.0f && ix0f <= (float)(Ww - 1)) ? 1.0f : 0.0f;
        float mx1 = (ix1f >= 0.0f && ix1f <= (float)(Ww - 1)) ? 1.0f : 0.0f;
        float my0 = (iy0f >= 0.0f && iy0f <= (float)(Hh - 1)) ? 1.0f : 0.0f;
        float my1 = (iy1f >= 0.0f && iy1f <= (float)(Hh - 1)) ? 1.0f : 0.0f;

        int x0 = (int)fminf(fmaxf(ix0f, 0.0f), (float)(Ww - 1));
        int x1 = (int)fminf(fmaxf(ix1f, 0.0f), (float)(Ww - 1));
        int y0 = (int)fminf(fmaxf(iy0f, 0.0f), (float)(Hh - 1));
        int y1 = (int)fminf(fmaxf(iy1f, 0.0f), (float)(Hh - 1));

        PixS p;
        p.w00 = wy0 * wx0 * (my0 * mx0);
        p.w01 = wy0 * wx1 * (my0 * mx1);
        p.w10 = wy1 * wx0 * (my1 * mx0);
        p.w11 = wy1 * wx1 * (my1 * mx1);

        int baseB = b * (Hh * Ww);
        p.o00 = (baseB + y0 * Ww + x0) * PIX_F4;
        p.o01 = (baseB + y0 * Ww + x1) * PIX_F4;
        p.o10 = (baseB + y1 * Ww + x0) * PIX_F4;
        p.o11 = (baseB + y1 * Ww + x1) * PIX_F4;
        p.ob  = pix * PIX_F4;

        sm[tid] = p;
    }
    __syncthreads();

    // ---- all 256 threads: (pixel, c4, t-pair) ----
    int pair = tid >> 7;          // 0: t0,t1   1: t2,t3 (+ t4 passthrough)
    int px   = (tid >> 4) & 7;
    int c4   = tid & 15;

    PixS p = sm[px];
    int o00 = p.o00 + c4;
    int o01 = p.o01 + c4;
    int o10 = p.o10 + c4;
    int o11 = p.o11 + c4;
    int ob  = p.ob  + c4;
    int tb  = pair << 5;          // float4 offset of first t-slice: 0 or 32

    // front-load 8 corner float4s (2 t-slices) + optional passthrough
    float4 a00 = __ldg(&in[o00 + tb]);
    float4 a01 = __ldg(&in[o01 + tb]);
    float4 a10 = __ldg(&in[o10 + tb]);
    float4 a11 = __ldg(&in[o11 + tb]);
    float4 b00 = __ldg(&in[o00 + tb + 16]);
    float4 b01 = __ldg(&in[o01 + tb + 16]);
    float4 b10 = __ldg(&in[o10 + tb + 16]);
    float4 b11 = __ldg(&in[o11 + tb + 16]);
    float4 cur;
    if (pair) cur = __ldcs(&in[ob + 64]);

    float4 r0, r1;
    r0.x = p.w00*a00.x + p.w01*a01.x + p.w10*a10.x + p.w11*a11.x;
    r0.y = p.w00*a00.y + p.w01*a01.y + p.w10*a10.y + p.w11*a11.y;
    r0.z = p.w00*a00.z + p.w01*a01.z + p.w10*a10.z + p.w11*a11.z;
    r0.w = p.w00*a00.w + p.w01*a01.w + p.w10*a10.w + p.w11*a11.w;
    r1.x = p.w00*b00.x + p.w01*b01.x + p.w10*b10.x + p.w11*b11.x;
    r1.y = p.w00*b00.y + p.w01*b01.y + p.w10*b10.y + p.w11*b11.y;
    r1.z = p.w00*b00.z + p.w01*b01.z + p.w10*b10.z + p.w11*b11.z;
    r1.w = p.w00*b00.w + p.w01*b01.w + p.w10*b10.w + p.w11*b11.w;

    __stcs(&out[ob + tb],      r0);
    __stcs(&out[ob + tb + 16], r1);
    if (pair) __stcs(&out[ob + 64], cur);
}

extern "C" void kernel_launch(void* const* d_in, const int* in_sizes, int n_in,
                              void* d_out, int out_size)
{
    const float4* in  = (const float4*)d_in[0];   // raw_bev_cache (4,200,200,5,64) f32
    const float*  ego = (const float*)d_in[1];    // delta_ego_motion (4,3) f32
    float4* out = (float4*)d_out;

    align_bev_v7<<<NBLOCKS, 256>>>(in, ego, out);
}